// round 8
// baseline (speedup 1.0000x reference)
#include <cuda_runtime.h>
#include <cuda_bf16.h>
#include <cstdint>

// Problem constants (fixed by the dataset)
#define CLASSES   128
#define M_IN      64      // inner dim (K)
#define N_OUT     32      // outputs per class
#define SPLIT     4       // blocks per class in main kernel
#define MAIN_THREADS  256 // 8 warps
#define WARP_BATCH 16     // samples per warp per pass
#define HIST_THREADS  1024
#define MAX_HIST_BLOCKS 1024

// ---------------- scratch (no allocations allowed) ----------------
__device__ int g_offsets[CLASSES + 1];
__device__ int g_cursor[CLASSES];
__device__ int g_perm[1 << 20];           // supports up to 1M samples
__device__ int g_blockcounts[MAX_HIST_BLOCKS * CLASSES];

// Detect whether the index buffer is int64 or int32.
// If int64 with small class values, every odd int32 word (LE high half) is 0.
__device__ __forceinline__ void detect_is64(const int* w, int nwords, int tid,
                                            int* flag) {
    if (tid < 32) {
        int idx = 2 * tid + 1;
        int v = (idx < nwords) ? w[idx] : 0;
        unsigned nz = __ballot_sync(0xFFFFFFFFu, v != 0);
        if (tid == 0) *flag = (nz == 0u) ? 1 : 0;
    }
}

__device__ __forceinline__ int load_class(const void* inds, int n, int is64) {
    int c;
    if (is64) c = (int)((const long long*)inds)[n];
    else      c = ((const int*)inds)[n];
    return c & (CLASSES - 1);   // defensive clamp
}

// ---------------- kernel 1: per-block histogram ----------------
__global__ void hist_kernel(const void* __restrict__ inds, int N) {
    __shared__ int s_cnt[CLASSES];
    __shared__ int s_is64;
    int t = threadIdx.x;
    if (t < CLASSES) s_cnt[t] = 0;
    detect_is64((const int*)inds, N, t, &s_is64);
    __syncthreads();
    int n = blockIdx.x * HIST_THREADS + t;
    if (n < N) atomicAdd(&s_cnt[load_class(inds, n, s_is64)], 1);
    __syncthreads();
    if (t < CLASSES) g_blockcounts[blockIdx.x * CLASSES + t] = s_cnt[t];
}

// ---------------- kernel 2: reduce + exclusive scan ----------------
__global__ void scan_kernel(int nblocks) {
    __shared__ int s[CLASSES];
    int t = threadIdx.x;   // 128 threads
    int sum = 0;
    for (int b = 0; b < nblocks; b++)
        sum += g_blockcounts[b * CLASSES + t];
    s[t] = sum;
    __syncthreads();
    #pragma unroll
    for (int off = 1; off < CLASSES; off <<= 1) {
        int v = (t >= off) ? s[t - off] : 0;
        __syncthreads();
        s[t] += v;
        __syncthreads();
    }
    int incl = s[t];
    g_offsets[t + 1] = incl;
    if (t == 0) g_offsets[0] = 0;
    g_cursor[t] = incl - sum;   // exclusive prefix
}

// ---------------- kernel 3: scatter (two-level) ----------------
__global__ void scatter_kernel(const void* __restrict__ inds, int N) {
    __shared__ int s_cnt[CLASSES];
    __shared__ int s_base[CLASSES];
    __shared__ int s_is64;
    int t = threadIdx.x;
    if (t < CLASSES) s_cnt[t] = 0;
    detect_is64((const int*)inds, N, t, &s_is64);
    __syncthreads();
    int n = blockIdx.x * HIST_THREADS + t;
    int c = 0, loc = 0;
    if (n < N) {
        c = load_class(inds, n, s_is64);
        loc = atomicAdd(&s_cnt[c], 1);
    }
    __syncthreads();
    if (t < CLASSES) s_base[t] = atomicAdd(&g_cursor[t], s_cnt[t]);
    __syncthreads();
    if (n < N) g_perm[s_base[c] + loc] = n;
}

// ---------------- kernel 4: main gathered GEMV (front-batched) ----------
// grid = CLASSES * SPLIT blocks, 256 threads (8 warps), up to 4 CTAs/SM.
// Warp handles 16 samples per pass (typically ONE pass total):
//   1. all 16 perm ids + all 16 x rows (8 LDG.128/lane, max MLP) issued
//      up front -> one exposed gather latency per warp pass,
//   2. one sync, then two back-to-back 8-sample FFMA passes (R2-proven
//      register-blocked compute, W broadcast-free padded shared rows),
//   3. coalesced 128B row stores.
__global__ void __launch_bounds__(MAIN_THREADS, 4)
main_kernel(const float* __restrict__ x,
            const float* __restrict__ W,
            const float* __restrict__ b,
            float* __restrict__ out) {
    __shared__ float W_sh[N_OUT * 68];          // padded rows: stride 68 floats
    __shared__ float b_sh[N_OUT];
    __shared__ float x_sh[8][WARP_BATCH][M_IN]; // [warp][sample][k]  32KB
    __shared__ int   n_idx[8][WARP_BATCH];

    const int tid  = threadIdx.x;
    const int w    = tid >> 5;
    const int lane = tid & 31;

    const int c = blockIdx.x / SPLIT;
    const int q = blockIdx.x % SPLIT;

    const int start = g_offsets[c];
    const int endc  = g_offsets[c + 1];
    const int total = endc - start;
    const int chunk = (total + SPLIT - 1) / SPLIT;
    const int s0 = start + q * chunk;
    const int s1 = min(endc, s0 + chunk);

    int base = s0 + w * WARP_BATCH;

    // ---- prologue: perm ids for pass 0 (before W staging: overlap chains)
    if (lane < WARP_BATCH && base < s1) {
        int rem0 = s1 - base; if (rem0 > WARP_BATCH) rem0 = WARP_BATCH;
        n_idx[w][lane] = g_perm[base + (lane < rem0 ? lane : rem0 - 1)];
    }

    // ---- stage W slice (2048 floats) as float4, padded rows
    const float4* Wg = reinterpret_cast<const float4*>(W + (size_t)c * (N_OUT * M_IN));
    #pragma unroll
    for (int i = 0; i < 2; i++) {
        int idx = tid + i * MAIN_THREADS;           // 0..511 float4s
        float4 v = Wg[idx];
        *reinterpret_cast<float4*>(&W_sh[(idx >> 4) * 68 + (idx & 15) * 4]) = v;
    }
    if (tid < N_OUT) b_sh[tid] = b[c * N_OUT + tid];
    __syncthreads();

    const float bias = b_sh[lane];

    for (; base < s1; base += 8 * WARP_BATCH) {
        int rem = s1 - base; if (rem > WARP_BATCH) rem = WARP_BATCH;

        if (base != s0 + w * WARP_BATCH) {          // pass>0: reload ids
            if (lane < WARP_BATCH)
                n_idx[w][lane] = g_perm[base + (lane < rem ? lane : rem - 1)];
            __syncwarp();
        } else {
            __syncwarp();                           // ids from prologue
        }

        // ---- front-batched x gather: 16 rows x 16 float4 = 256 float4,
        //      8 per lane, ALL issued before any STS (MLP=8/lane).
        float4 r[8];
        #pragma unroll
        for (int i = 0; i < 8; i++) {
            int t2  = lane + 32 * i;                // 0..255
            int row = t2 >> 4;
            int kp  = t2 & 15;
            int n   = n_idx[w][row];
            r[i] = *reinterpret_cast<const float4*>(x + (size_t)n * M_IN + kp * 4);
        }
        #pragma unroll
        for (int i = 0; i < 8; i++) {
            int t2  = lane + 32 * i;
            int row = t2 >> 4;
            int kp  = t2 & 15;
            *reinterpret_cast<float4*>(&x_sh[w][row][kp * 4]) = r[i];
        }
        __syncwarp();

        // ---- two 8-sample compute passes, back to back (no memory waits)
        #pragma unroll
        for (int half = 0; half < 2; half++) {
            float acc0 = 0.f, acc1 = 0.f, acc2 = 0.f, acc3 = 0.f;
            float acc4 = 0.f, acc5 = 0.f, acc6 = 0.f, acc7 = 0.f;
            const float* wrow = &W_sh[lane * 68];
            #pragma unroll
            for (int k4 = 0; k4 < 16; k4++) {
                float4 wv = *reinterpret_cast<const float4*>(wrow + k4 * 4);
                #pragma unroll
                for (int s = 0; s < 8; s++) {
                    float4 xv = *reinterpret_cast<const float4*>(
                        &x_sh[w][half * 8 + s][k4 * 4]);
                    float a = (s==0)?acc0:(s==1)?acc1:(s==2)?acc2:(s==3)?acc3:
                              (s==4)?acc4:(s==5)?acc5:(s==6)?acc6:acc7;
                    a = fmaf(wv.x, xv.x, a);
                    a = fmaf(wv.y, xv.y, a);
                    a = fmaf(wv.z, xv.z, a);
                    a = fmaf(wv.w, xv.w, a);
                    if (s==0) acc0=a; else if (s==1) acc1=a; else if (s==2) acc2=a;
                    else if (s==3) acc3=a; else if (s==4) acc4=a; else if (s==5) acc5=a;
                    else if (s==6) acc6=a; else acc7=a;
                }
            }
            float accs[8] = {acc0,acc1,acc2,acc3,acc4,acc5,acc6,acc7};
            #pragma unroll
            for (int s = 0; s < 8; s++) {
                int gs = half * 8 + s;
                if (gs < rem) {
                    int n = n_idx[w][gs];
                    out[(size_t)n * N_OUT + lane] = accs[s] + bias;
                }
            }
        }
        __syncwarp();   // all lanes done with x_sh before next pass overwrite
    }
}

// ---------------- launch ----------------
extern "C" void kernel_launch(void* const* d_in, const int* in_sizes, int n_in,
                              void* d_out, int out_size) {
    const float* x    = (const float*)d_in[0];
    const void*  inds = d_in[1];
    const float* W    = (const float*)d_in[2];
    const float* b    = (const float*)d_in[3];
    float*       out  = (float*)d_out;
    const int N = in_sizes[1];

    int hist_blocks = (N + HIST_THREADS - 1) / HIST_THREADS;
    if (hist_blocks > MAX_HIST_BLOCKS) hist_blocks = MAX_HIST_BLOCKS;
    hist_kernel<<<hist_blocks, HIST_THREADS>>>(inds, N);
    scan_kernel<<<1, CLASSES>>>(hist_blocks);
    scatter_kernel<<<hist_blocks, HIST_THREADS>>>(inds, N);
    main_kernel<<<CLASSES * SPLIT, MAIN_THREADS>>>(x, W, b, out);
}